// round 15
// baseline (speedup 1.0000x reference)
#include <cuda_runtime.h>
#include <cuda_fp16.h>
#include <cstdint>

#define NNODES 16384
#define HD 64
#define TLEN 12
#define NHEADS 8

typedef uint32_t u32;

// ---------------- device globals (allocation-free scratch) ----------------
__device__ __half  g_wh[2 * 2 * 8 * 256 * 64];  // [(l*2+s)*8+a][row-perm 256][64] fp16
__device__ __half2 g_bias2[2 * 8 * 3 * 32];     // 0.5*(b_ih+b_hh) half2 pairs, gates i,f,o
__device__ float   g_biasg[2 * 8 * 64];         // g-gate bias fp32
__device__ __half  g_xh[TLEN * NNODES * HD];    // x fp16
__device__ __half  g_hsh[8 * TLEN * NNODES * HD]; // layer-1 h fp16, ch = a*12+t

// ---------------- helpers ----------------
__device__ __forceinline__ u32 swz(u32 o) { return o ^ ((o >> 3) & 0x70); }
__device__ __forceinline__ float tanha(float x) {
    float r; asm("tanh.approx.f32 %0, %1;" : "=f"(r) : "f"(x)); return r;
}
__device__ __forceinline__ __half2 h2tanh_(__half2 x) {
    u32 r, xi = *(u32*)&x;
    asm("tanh.approx.f16x2 %0, %1;" : "=r"(r) : "r"(xi));
    return *(__half2*)&r;
}
__device__ __forceinline__ void cpasync16(u32 saddr, const void* gaddr) {
    asm volatile("cp.async.cg.shared.global [%0], [%1], 16;" :: "r"(saddr), "l"(gaddr));
}
#define CP_COMMIT() asm volatile("cp.async.commit_group;" ::: "memory")
#define CP_WAIT(n)  asm volatile("cp.async.wait_group %0;" :: "n"(n) : "memory")
#define PH()        asm volatile("bar.sync 1, 512;" ::: "memory")

__device__ __forceinline__ void ldsm4(u32& r0, u32& r1, u32& r2, u32& r3, u32 addr) {
    asm volatile("ldmatrix.sync.aligned.m8n8.x4.shared.b16 {%0,%1,%2,%3}, [%4];"
                 : "=r"(r0), "=r"(r1), "=r"(r2), "=r"(r3) : "r"(addr));
}

// ---------------- prep kernels ----------------
// row perm: rp = (u>>4)*64 + g*16 + (u&15)
__global__ void prep_w_kernel(const float* __restrict__ Wih, const float* __restrict__ Whh) {
    int idx = blockIdx.x * 256 + threadIdx.x;        // 524288
    if (idx >= 2 * 2 * 8 * 256 * 64) return;
    int j  = idx & 63;
    int rp = (idx >> 6) & 255;
    int a  = (idx >> 14) & 7;
    int s  = (idx >> 17) & 1;
    int l  = idx >> 18;
    int ublk = rp >> 6, rem = rp & 63;
    int g = rem >> 4, u = (ublk << 4) | (rem & 15);
    const float* W = s ? Whh : Wih;
    float v = W[(((size_t)(l * 8 + a)) * 256 + (g * 64 + u)) * 64 + j];
    g_wh[((size_t)((l * 2 + s) * 8 + a)) * 16384 + rp * 64 + j] = __float2half_rn(v);
}

__global__ void prep_bias_kernel(const float* __restrict__ bih, const float* __restrict__ bhh) {
    int idx = blockIdx.x * 256 + threadIdx.x;
    if (idx < 1536) {
        int u2 = idx & 31;
        int gs = (idx >> 5) % 3;         // 0:i 1:f 2:o
        int la = idx / 96;
        const int gmap[3] = {0, 1, 3};
        int g = gmap[gs];
        int b0 = la * 256 + g * 64 + u2 * 2;
        float v0 = 0.5f * (bih[b0] + bhh[b0]);
        float v1 = 0.5f * (bih[b0 + 1] + bhh[b0 + 1]);
        g_bias2[idx] = __floats2half2_rn(v0, v1);
    }
    if (idx < 1024) {
        int u = idx & 63, la = idx >> 6;
        int b = la * 256 + 2 * 64 + u;
        g_biasg[idx] = bih[b] + bhh[b];
    }
}

__global__ void prep_x_kernel(const float* __restrict__ x) {
    int idx = blockIdx.x * 256 + threadIdx.x;
    if (idx < TLEN * NNODES * HD) g_xh[idx] = __float2half_rn(x[idx]);
}

// ---------------- fused LSTM: N-half phases, double-buffered h ----------------
#define S_W    0u          // 4 x 32KB weight chunks (l*2+c)
#define S_BIAS 131072u     // 768B half2 bias + 512B g-bias
#define S_WG   133120u     // per-wg 48KB: X[2]x8K, H0[2]x8K, H1[2]x8K
#define WG_SZ  49152u
#define SMEM_TOTAL (133120 + 2 * 49152)   // 231424 <= 232448

__global__ void __launch_bounds__(512, 1)
lstm_fused(const float* __restrict__ h0g, const float* __restrict__ c0)
{
    extern __shared__ __align__(1024) char smem[];
    const u32 sb = (u32)__cvta_generic_to_shared(smem);

    const int tid  = threadIdx.x;
    const int lane = tid & 31;
    const int wg   = tid >> 8;           // 0/1: independent 64-node streams
    const int wtid = tid & 255;
    const int wl   = (tid >> 5) & 7;
    const int um   = wl & 3;             // M block (16 rows)
    const int un   = wl >> 2;            // N block (64 cols within the 128-col phase)
    const int a    = blockIdx.y;
    const int tile = blockIdx.x * 128;
    const int nb   = tile + wg * 64;

    const u32 WGB = sb + S_WG + wg * WG_SZ;
    const u32 AX  = WGB;                 // 2 x 8KB
    const u32 AH0 = WGB + 16384;         // 2 x 8KB
    const u32 AH1 = WGB + 32768;         // 2 x 8KB
    char* WGP = smem + S_WG + wg * WG_SZ;

    // ---- stage weights (whole CTA, 4 x 32KB) ----
    #pragma unroll
    for (int i = 0; i < 16; i++) {
        int idx = tid + i * 512;
        int ci = idx >> 11, rem = idx & 2047;
        int r = rem >> 3, j = rem & 7;
        cpasync16(sb + S_W + ci * 32768 + swz((u32)(r * 128 + j * 16)),
                  g_wh + ((size_t)(ci * 8 + a)) * 16384 + r * 64 + j * 8);
    }
    // ---- stage x(0) (buf 0) for this wg ----
    #pragma unroll
    for (int i = 0; i < 2; i++) {
        int idx = wtid + i * 256;
        int r = idx >> 3, j = idx & 7;
        cpasync16(AX + swz((u32)(r * 128 + j * 16)),
                  g_xh + ((size_t)nb + r) * 64 + j * 8);
    }
    CP_COMMIT();

    // ---- bias -> smem ----
    if (tid < 192) {
        int l = tid / 96, r = tid % 96;
        ((__half2*)(smem + S_BIAS))[tid] = g_bias2[(l * 8 + a) * 96 + r];
    }
    if (tid >= 256 && tid < 384) {
        int k = tid - 256;
        int l = k >> 6;
        ((float*)(smem + S_BIAS + 768))[k] = g_biasg[(l * 8 + a) * 64 + (k & 63)];
    }

    // ---- h0 fp32 -> fp16 tiles (buf 0 of AH0 / AH1) ----
    {
        int row = wtid & 63;
        int cb  = (wtid >> 6) * 16;
        #pragma unroll
        for (int l = 0; l < 2; l++) {
            const float* src = h0g + (((size_t)(a * 2 + l)) * NNODES + nb + row) * 64 + cb;
            char* dst = WGP + (l ? 32768 : 16384);
            #pragma unroll
            for (int k = 0; k < 4; k++) {
                float4 v = *(const float4*)(src + k * 4);
                u32 off = (u32)(row * 128 + (cb + k * 4) * 2);
                *(__half2*)(dst + swz(off))     = __floats2half2_rn(v.x, v.y);
                *(__half2*)(dst + swz(off + 4)) = __floats2half2_rn(v.z, v.w);
            }
        }
    }

    // ---- c state in registers: ci = l*8 + p*4 + rw*2 + hi ----
    float2 cst[16];
    #pragma unroll
    for (int l = 0; l < 2; l++)
        #pragma unroll
        for (int p = 0; p < 2; p++)
            #pragma unroll
            for (int rw = 0; rw < 2; rw++)
                #pragma unroll
                for (int hi = 0; hi < 2; hi++) {
                    int nn = um * 16 + (lane >> 2) + rw * 8;
                    int u0 = (2 * p + un) * 16 + hi * 8 + (lane & 3) * 2;
                    cst[l * 8 + p * 4 + rw * 2 + hi] =
                        *(const float2*)&c0[(((size_t)(a * 2 + l)) * NNODES + nb + nn) * 64 + u0];
                }

    CP_WAIT(0);
    __syncthreads();

    float acc[8][4];
    const __half2 H05 = __floats2half2_rn(0.5f, 0.5f);

    if (wg == 1) PH();   // wg1 one slot behind -> G of one wg overlaps E of the other

    for (int t = 0; t < TLEN; t++) {
        if (t + 1 < TLEN) {
            #pragma unroll
            for (int i = 0; i < 2; i++) {
                int idx = wtid + i * 256;
                int r = idx >> 3, j = idx & 7;
                cpasync16(AX + (((t + 1) & 1) * 8192) + swz((u32)(r * 128 + j * 16)),
                          g_xh + (((size_t)(t + 1) * NNODES) + nb + r) * 64 + j * 8);
            }
            CP_COMMIT();
            CP_WAIT(1);
        } else {
            CP_WAIT(0);
        }

        #pragma unroll
        for (int l = 0; l < 2; l++) {
            const u32 Ab0 = l ? (AH0 + (((t + 1) & 1) * 8192)) : (AX + ((t & 1) * 8192));
            const u32 Ab1 = l ? (AH1 + ((t & 1) * 8192))       : (AH0 + ((t & 1) * 8192));
            char* hdst = WGP + (l ? 32768 : 16384) + (((t + 1) & 1) * 8192);

            #pragma unroll
            for (int p = 0; p < 2; p++) {
                PH();   // ---- GEMM half-slot ----

                #pragma unroll
                for (int n8 = 0; n8 < 8; n8++)
                    #pragma unroll
                    for (int e = 0; e < 4; e++) acc[n8][e] = 0.0f;

                #pragma unroll
                for (int c = 0; c < 2; c++) {
                    const u32 Ab = c ? Ab1 : Ab0;
                    const u32 Wb = sb + S_W + (u32)((l * 2 + c) * 32768 + p * 16384 + un * 8192);
                    #pragma unroll
                    for (int ks = 0; ks < 4; ks++) {
                        const int kb = ks * 32;
                        u32 a0, a1, a2, a3;
                        ldsm4(a0, a1, a2, a3,
                              Ab + swz((u32)((um * 16 + (lane & 15)) * 128 + kb + ((lane >> 4) << 4))));
                        #pragma unroll
                        for (int i = 0; i < 4; i++) {
                            u32 b0, b1, b2, b3;
                            ldsm4(b0, b1, b2, b3,
                                  Wb + swz((u32)((i * 16 + (lane & 15)) * 128 + kb + ((lane >> 4) << 4))));
                            asm volatile(
                                "mma.sync.aligned.m16n8k16.row.col.f32.f16.f16.f32 "
                                "{%0,%1,%2,%3},{%4,%5,%6,%7},{%8,%9},{%0,%1,%2,%3};"
                                : "+f"(acc[i*2][0]), "+f"(acc[i*2][1]),
                                  "+f"(acc[i*2][2]), "+f"(acc[i*2][3])
                                : "r"(a0), "r"(a1), "r"(a2), "r"(a3), "r"(b0), "r"(b2));
                            asm volatile(
                                "mma.sync.aligned.m16n8k16.row.col.f32.f16.f16.f32 "
                                "{%0,%1,%2,%3},{%4,%5,%6,%7},{%8,%9},{%0,%1,%2,%3};"
                                : "+f"(acc[i*2+1][0]), "+f"(acc[i*2+1][1]),
                                  "+f"(acc[i*2+1][2]), "+f"(acc[i*2+1][3])
                                : "r"(a0), "r"(a1), "r"(a2), "r"(a3), "r"(b1), "r"(b3));
                        }
                    }
                }

                PH();   // ---- epilogue half-slot ----
                {
                    const __half2* sB2 = (const __half2*)(smem + S_BIAS) + l * 96;
                    const float*   sBg = (const float*)(smem + S_BIAS + 768) + l * 64;
                    __half2* hs_o = (__half2*)(g_hsh + (((size_t)(a * TLEN + t)) * NNODES + nb) * 64);
                    #pragma unroll
                    for (int rw = 0; rw < 2; rw++) {
                        const int nn = um * 16 + (lane >> 2) + rw * 8;
                        const int e = rw * 2;
                        #pragma unroll
                        for (int hi = 0; hi < 2; hi++) {
                            const int u0 = (2 * p + un) * 16 + hi * 8 + (lane & 3) * 2;
                            const int bidx = u0 >> 1;
                            const int ci = l * 8 + p * 4 + rw * 2 + hi;
                            float2 cc = cst[ci];
                            __half2 zi2 = __floats2half2_rn(acc[0 + hi][e], acc[0 + hi][e + 1]);
                            __half2 zf2 = __floats2half2_rn(acc[2 + hi][e], acc[2 + hi][e + 1]);
                            __half2 zo2 = __floats2half2_rn(acc[6 + hi][e], acc[6 + hi][e + 1]);
                            __half2 si2 = __hfma2(h2tanh_(__hfma2(zi2, H05, sB2[bidx])),      H05, H05);
                            __half2 sf2 = __hfma2(h2tanh_(__hfma2(zf2, H05, sB2[32 + bidx])), H05, H05);
                            __half2 so2 = __hfma2(h2tanh_(__hfma2(zo2, H05, sB2[64 + bidx])), H05, H05);
                            float2 si = __half22float2(si2);
                            float2 sf = __half22float2(sf2);
                            float2 so = __half22float2(so2);
                            float2 bg = *(const float2*)&sBg[u0];
                            float tg0 = tanha(acc[4 + hi][e]     + bg.x);
                            float tg1 = tanha(acc[4 + hi][e + 1] + bg.y);
                            float cn0 = __fmaf_rn(sf.x, cc.x, si.x * tg0);
                            float cn1 = __fmaf_rn(sf.y, cc.y, si.y * tg1);
                            float hn0 = so.x * tanha(cn0);
                            float hn1 = so.y * tanha(cn1);
                            cst[ci] = make_float2(cn0, cn1);
                            __half2 hp = __floats2half2_rn(hn0, hn1);
                            *(__half2*)(hdst + swz((u32)(nn * 128 + u0 * 2))) = hp;
                            if (l == 1) hs_o[(nn * 64 + u0) >> 1] = hp;
                        }
                    }
                }
            }
        }
    }
    if (wg == 0) PH();   // balance wg1's leading phase
}

// ---------------- 1x1 conv over channels (heads*T -> T), fp16 input ----------------
__global__ void conv_kernel(const float* __restrict__ conv_w,
                            const float* __restrict__ conv_b,
                            float* __restrict__ out)
{
    __shared__ float ws[TLEN * 96];
    const int tid = threadIdx.x;
    for (int i = tid; i < TLEN * 96; i += 256) ws[i] = conv_w[i];
    __syncthreads();

    const size_t P = (size_t)NNODES * HD;
    const size_t base = ((size_t)blockIdx.x * 256 + tid) * 4;

    float4 accv[TLEN];
    #pragma unroll
    for (int o = 0; o < TLEN; o++) {
        float b = conv_b[o];
        accv[o] = make_float4(b, b, b, b);
    }
    #pragma unroll 4
    for (int c = 0; c < 96; c++) {
        uint2 raw = *(const uint2*)&g_hsh[(size_t)c * P + base];
        float2 f0 = __half22float2(*(__half2*)&raw.x);
        float2 f1 = __half22float2(*(__half2*)&raw.y);
        #pragma unroll
        for (int o = 0; o < TLEN; o++) {
            float wv = ws[o * 96 + c];
            accv[o].x += wv * f0.x; accv[o].y += wv * f0.y;
            accv[o].z += wv * f1.x; accv[o].w += wv * f1.y;
        }
    }
    #pragma unroll
    for (int o = 0; o < TLEN; o++)
        *(float4*)&out[(size_t)o * P + base] = accv[o];
}

extern "C" void kernel_launch(void* const* d_in, const int* in_sizes, int n_in,
                              void* d_out, int out_size)
{
    const float* x   = (const float*)d_in[0];
    const float* Wih = (const float*)d_in[1];
    const float* Whh = (const float*)d_in[2];
    const float* bih = (const float*)d_in[3];
    const float* bhh = (const float*)d_in[4];
    const float* h0  = (const float*)d_in[5];
    const float* c0  = (const float*)d_in[6];
    const float* cw  = (const float*)d_in[7];
    const float* cb  = (const float*)d_in[8];
    float* out = (float*)d_out;

    cudaFuncSetAttribute(lstm_fused, cudaFuncAttributeMaxDynamicSharedMemorySize, SMEM_TOTAL);

    prep_w_kernel<<<2048, 256>>>(Wih, Whh);
    prep_bias_kernel<<<8, 256>>>(bih, bhh);
    prep_x_kernel<<<(TLEN * NNODES * HD + 255) / 256, 256>>>(x);

    dim3 grid(NNODES / 128, NHEADS);
    lstm_fused<<<grid, 512, SMEM_TOTAL>>>(h0, c0);

    conv_kernel<<<(NNODES * HD) / 1024, 256>>>(cw, cb, out);
}